// round 4
// baseline (speedup 1.0000x reference)
#include <cuda_runtime.h>
#include <math.h>

constexpr int T = 512, B = 32, DIN = 41, H = 800;
constexpr int NBLK = 100, UPB = 16;          // persistent recurrence grid
constexpr int SH_STR = 804;                  // h smem row stride (floats)
constexpr int SX_STR = 44;                   // padded input K
typedef unsigned long long ull;

// ---------------- scratch (static device globals) ----------------
__device__ float g_hstate[2][2][B][H];       // [phase][dir][b][k]
__device__ float g_cstate[2][H][B];          // [dir][unit][b]
__device__ float g_h1[T][B][2 * H];
__device__ float g_h2[T][B][2 * H];
__device__ float g_xs1[2][T][4 * H][B];
__device__ float g_Wp[2][4 * H][SX_STR];     // zero-padded Wih (layer 0)
__device__ float g_ang[T][B][3];
__device__ int   g_bar[2][T];

// ---------------- helpers ----------------
__device__ __forceinline__ void ffma2(ull& d, ull a, ull b) {
    asm("fma.rn.f32x2 %0, %1, %2, %0;" : "+l"(d) : "l"(a), "l"(b));
}
__device__ __forceinline__ float hadd(ull v) {
    float lo, hi;
    asm("mov.b64 {%0,%1}, %2;" : "=f"(lo), "=f"(hi) : "l"(v));
    return lo + hi;
}
__device__ __forceinline__ float sigm(float x) { return 1.0f / (1.0f + expf(-x)); }

// 4-k micro-step: two weight rows vs one h float4 (2 k-pairs)
#define STEP4(HPTR, A0, A1)                                                  \
    {                                                                        \
        float4 hv = *(const float4*)(HPTR);                                  \
        ull hlo = ((const ull*)&hv)[0], hhi = ((const ull*)&hv)[1];          \
        ffma2(A0, w0a, hlo); ffma2(A0, w0b, hhi);                            \
        ffma2(A1, w1a, hlo); ffma2(A1, w1b, hhi);                            \
    }

// ---------------- init kernels ----------------
__global__ void zero_kernel(int zero_bar) {
    int i = blockIdx.x * blockDim.x + threadIdx.x;
    if (i < 2 * 2 * B * H) ((float*)g_hstate)[i] = 0.0f;
    if (i < 2 * H * B)     ((float*)g_cstate)[i] = 0.0f;
    if (zero_bar && i < 2 * T) ((int*)g_bar)[i] = 0;
}

__global__ void prep_wp(const float* __restrict__ Wf, const float* __restrict__ Wb) {
    int i = blockIdx.x * blockDim.x + threadIdx.x;
    if (i >= 2 * 4 * H * SX_STR) return;
    int dir = i / (4 * H * SX_STR);
    int rem = i % (4 * H * SX_STR);
    int r = rem / SX_STR, k = rem % SX_STR;
    const float* W = dir ? Wb : Wf;
    ((float*)g_Wp)[i] = (k < DIN) ? W[r * DIN + k] : 0.0f;
}

// ---------------- persistent bi-LSTM layer ----------------
// grid 100 blocks (50/dir, 16 units each), 256 threads = (u<16, gp<2, bq<8).
// Thread computes gates {2gp, 2gp+1} of unit u for batches {bq, bq+8, bq+16, bq+24}.
template <int LAYER>
__global__ void __launch_bounds__(256, 1) lstm_persist(
    const float* __restrict__ x,
    const float* __restrict__ Whh_f, const float* __restrict__ b_f,
    const float* __restrict__ Whh_b, const float* __restrict__ b_b)
{
    extern __shared__ float smem[];
    float* sh = smem;                        // 32 * 804
    float* sx = smem + 32 * SH_STR;          // 32 * 44
    float* sg = sx + 32 * SX_STR;            // 16 * 4 * 33

    const int tid = threadIdx.x;
    const int u = tid >> 4, gp = (tid >> 3) & 1, bq = tid & 7;
    const int blk = blockIdx.x;
    const int dir = (blk >= 50);
    const int ug = (dir ? blk - 50 : blk) * UPB + u;

    const float* __restrict__ Whh = dir ? Whh_b : Whh_f;
    const float* __restrict__ bia = dir ? b_b : b_f;
    const int g0 = 2 * gp, g1 = g0 + 1;
    const int r0 = g0 * H + ug, r1 = g1 * H + ug;
    const float* w0p = Whh + (size_t)r0 * H;
    const float* w1p = Whh + (size_t)r1 * H;
    const float* wp0 = &g_Wp[dir][r0][0];
    const float* wp1 = &g_Wp[dir][r1][0];
    const float bv0 = bia[r0], bv1 = bia[r1];

    for (int s = 0; s < T; s++) {
        const int t = dir ? (T - 1 - s) : s;
        const int ph = s & 1;

        // stage h (bypass L1: written by other SMs last step)
        const float* hsrc = &g_hstate[ph][dir][0][0];
        for (int i = tid; i < 32 * (H / 4); i += 256) {
            int b = i / (H / 4), kq = i % (H / 4);
            float4 v = __ldcg((const float4*)(hsrc + b * H + kq * 4));
            *(float4*)&sh[b * SH_STR + kq * 4] = v;
        }
        if (LAYER == 0) {
            for (int i = tid; i < 32 * SX_STR; i += 256) {
                int b = i / SX_STR, k = i % SX_STR;
                sx[i] = (k < DIN) ? __ldg(&x[(t * B + b) * DIN + k]) : 0.0f;
            }
        }
        __syncthreads();

        ull a00 = 0, a01 = 0, a02 = 0, a03 = 0;
        ull a10 = 0, a11 = 0, a12 = 0, a13 = 0;

#pragma unroll 2
        for (int k = 0; k < H; k += 4) {
            float4 w0v = __ldg((const float4*)(w0p + k));
            float4 w1v = __ldg((const float4*)(w1p + k));
            ull w0a = ((const ull*)&w0v)[0], w0b = ((const ull*)&w0v)[1];
            ull w1a = ((const ull*)&w1v)[0], w1b = ((const ull*)&w1v)[1];
            const float* hk = &sh[bq * SH_STR + k];
            STEP4(hk,                 a00, a10);
            STEP4(hk +  8 * SH_STR,   a01, a11);
            STEP4(hk + 16 * SH_STR,   a02, a12);
            STEP4(hk + 24 * SH_STR,   a03, a13);
        }
        if (LAYER == 0) {
#pragma unroll
            for (int k = 0; k < SX_STR; k += 4) {
                float4 w0v = *(const float4*)(wp0 + k);
                float4 w1v = *(const float4*)(wp1 + k);
                ull w0a = ((const ull*)&w0v)[0], w0b = ((const ull*)&w0v)[1];
                ull w1a = ((const ull*)&w1v)[0], w1b = ((const ull*)&w1v)[1];
                const float* hk = &sx[bq * SX_STR + k];
                STEP4(hk,                 a00, a10);
                STEP4(hk +  8 * SX_STR,   a01, a11);
                STEP4(hk + 16 * SX_STR,   a02, a12);
                STEP4(hk + 24 * SX_STR,   a03, a13);
            }
        }

        // write gate pre-activations
        float va[4] = {hadd(a00), hadd(a01), hadd(a02), hadd(a03)};
        float vb[4] = {hadd(a10), hadd(a11), hadd(a12), hadd(a13)};
#pragma unroll
        for (int i = 0; i < 4; i++) {
            int b = bq + 8 * i;
            float e0 = va[i] + bv0, e1 = vb[i] + bv1;
            if (LAYER == 1) {
                e0 += __ldg(&g_xs1[dir][t][r0][b]);
                e1 += __ldg(&g_xs1[dir][t][r1][b]);
            }
            sg[(u * 4 + g0) * 33 + b] = e0;
            sg[(u * 4 + g1) * 33 + b] = e1;
        }
        __syncthreads();

        // cell update: 2 batches per thread
#pragma unroll
        for (int j = 0; j < 2; j++) {
            int b = bq + 8 * gp + 16 * j;
            float gi = sg[(u * 4 + 0) * 33 + b];
            float gf = sg[(u * 4 + 1) * 33 + b];
            float gg = sg[(u * 4 + 2) * 33 + b];
            float go = sg[(u * 4 + 3) * 33 + b];
            float c  = g_cstate[dir][ug][b];
            float cn = sigm(gf) * c + sigm(gi) * tanhf(gg);
            float hn = sigm(go) * tanhf(cn);
            g_cstate[dir][ug][b] = cn;
            g_hstate[ph ^ 1][dir][b][ug] = hn;
            if (LAYER == 0) g_h1[t][b][dir * H + ug] = hn;
            else            g_h2[t][b][dir * H + ug] = hn;
        }
        __threadfence();
        __syncthreads();

        if (s < T - 1) {
            if (tid == 0) {
                atomicAdd(&g_bar[LAYER][s], 1);
                while (*(volatile int*)&g_bar[LAYER][s] < NBLK) {}
            }
            __syncthreads();
        }
    }
}

// ---------------- xs1 = Wih1 @ h1 (parallel GEMM) ----------------
// grid (50, 512, 2), 256 threads = (rp<32, bq<8): 2 rows x 4 strided batches.
__global__ void __launch_bounds__(256) xs1_gemm(
    const float* __restrict__ Wf, const float* __restrict__ Wb)
{
    const int gt = blockIdx.x, t = blockIdx.y, dir = blockIdx.z;
    const float* __restrict__ W = dir ? Wb : Wf;
    __shared__ alignas(16) float sh[32 * 164];

    const int tid = threadIdx.x, rp = tid >> 3, bq = tid & 7;
    const int r0 = gt * 64 + rp * 2, r1 = r0 + 1;
    const float* w0p = W + (size_t)r0 * (2 * H);
    const float* w1p = W + (size_t)r1 * (2 * H);

    ull a00 = 0, a01 = 0, a02 = 0, a03 = 0;
    ull a10 = 0, a11 = 0, a12 = 0, a13 = 0;

    for (int k0 = 0; k0 < 2 * H; k0 += 160) {
        __syncthreads();
        for (int i = tid; i < 32 * 40; i += 256) {
            int b = i / 40, kq = i % 40;
            *(float4*)&sh[b * 164 + kq * 4] =
                __ldg((const float4*)(&g_h1[t][b][k0 + kq * 4]));
        }
        __syncthreads();
#pragma unroll 2
        for (int k = 0; k < 160; k += 4) {
            float4 w0v = __ldg((const float4*)(w0p + k0 + k));
            float4 w1v = __ldg((const float4*)(w1p + k0 + k));
            ull w0a = ((const ull*)&w0v)[0], w0b = ((const ull*)&w0v)[1];
            ull w1a = ((const ull*)&w1v)[0], w1b = ((const ull*)&w1v)[1];
            const float* hk = &sh[bq * 164 + k];
            STEP4(hk,            a00, a10);
            STEP4(hk +  8 * 164, a01, a11);
            STEP4(hk + 16 * 164, a02, a12);
            STEP4(hk + 24 * 164, a03, a13);
        }
    }
    float va[4] = {hadd(a00), hadd(a01), hadd(a02), hadd(a03)};
    float vb[4] = {hadd(a10), hadd(a11), hadd(a12), hadd(a13)};
#pragma unroll
    for (int i = 0; i < 4; i++) {
        int b = bq + 8 * i;
        g_xs1[dir][t][r0][b] = va[i];
        g_xs1[dir][t][r1][b] = vb[i];
    }
}

// ---------------- logits -> softmax-folded atan2 -> angles ----------------
__global__ void __launch_bounds__(640) logits_angles(
    const float* __restrict__ Wl, const float* __restrict__ bl,
    const float* __restrict__ alphabet)
{
    const int t = blockIdx.x, tid = threadIdx.x;
    __shared__ float sl[32][21];
    __shared__ float ssin[20][3], scos[20][3];

    if (tid < 60) {
        int a = tid / 3, j = tid % 3;
        float v = alphabet[tid];
        ssin[a][j] = sinf(v); scos[a][j] = cosf(v);
    }
    {
        int a = tid >> 5, b = tid & 31;
        float acc = 0.0f;
        for (int k = 0; k < 2 * H; k += 4) {
            float4 hv = __ldg((const float4*)&g_h2[t][b][k]);
            float4 wv = __ldg((const float4*)&Wl[a * 2 * H + k]);
            acc += hv.x * wv.x + hv.y * wv.y + hv.z * wv.z + hv.w * wv.w;
        }
        sl[b][a] = acc + __ldg(&bl[a]);
    }
    __syncthreads();

    if (tid < 32) {
        int b = tid;
        float m = -1e30f;
#pragma unroll
        for (int a = 0; a < 20; a++) m = fmaxf(m, sl[b][a]);
        float ys[3] = {0, 0, 0}, xc[3] = {0, 0, 0};
#pragma unroll
        for (int a = 0; a < 20; a++) {
            float e = expf(sl[b][a] - m);   // softmax normalizer cancels in atan2
#pragma unroll
            for (int j = 0; j < 3; j++) { ys[j] += e * ssin[a][j]; xc[j] += e * scos[a][j]; }
        }
#pragma unroll
        for (int j = 0; j < 3; j++) g_ang[t][b][j] = atan2f(ys[j], xc[j]);
    }
}

// ---------------- NeRF coordinate extension ----------------
__global__ void coord_scan_kernel(float* __restrict__ out)
{
    const int b = threadIdx.x;  // 32 lanes = batch
    const float rl[3] = {1.458f, 1.525f, 1.33f};
    const float th[3] = {2.124f, 1.941f, 2.028f};
    float rct[3], rst[3];
#pragma unroll
    for (int j = 0; j < 3; j++) { rct[j] = rl[j] * cosf(th[j]); rst[j] = rl[j] * sinf(th[j]); }

    float ax = 0.f, ay = 0.f, az = 0.f;
    float bx = 1.458f, by = 0.f, bz = 0.f;
    float cx = 2.f, cy = 1.f, cz = 0.f;

    for (int n = 0; n < 3 * T; n++) {
        int tt = n / 3, j = n - 3 * tt;
        float phi = g_ang[tt][b][j];
        float bcx = cx - bx, bcy = cy - by, bcz = cz - bz;
        float inv = 1.0f / sqrtf(bcx * bcx + bcy * bcy + bcz * bcz);
        bcx *= inv; bcy *= inv; bcz *= inv;
        float abx = bx - ax, aby = by - ay, abz = bz - az;
        float nx = aby * bcz - abz * bcy;
        float ny = abz * bcx - abx * bcz;
        float nz = abx * bcy - aby * bcx;
        inv = 1.0f / sqrtf(nx * nx + ny * ny + nz * nz);
        nx *= inv; ny *= inv; nz *= inv;
        float mx = ny * bcz - nz * bcy;
        float my = nz * bcx - nx * bcz;
        float mz = nx * bcy - ny * bcx;
        float sphi, cphi;
        sincosf(phi, &sphi, &cphi);
        float dx = cx - rct[j] * bcx + rst[j] * (cphi * mx + sphi * nx);
        float dy = cy - rct[j] * bcy + rst[j] * (cphi * my + sphi * ny);
        float dz = cz - rct[j] * bcz + rst[j] * (cphi * mz + sphi * nz);
        float* o = out + (n * B + b) * 3;
        o[0] = dx; o[1] = dy; o[2] = dz;
        ax = bx; ay = by; az = bz;
        bx = cx; by = cy; bz = cz;
        cx = dx; cy = dy; cz = dz;
    }
}

// ---------------- launch (8 graph nodes) ----------------
extern "C" void kernel_launch(void* const* d_in, const int* in_sizes, int n_in,
                              void* d_out, int out_size)
{
    const float* x      = (const float*)d_in[0];
    const float* Wih_f0 = (const float*)d_in[1];
    const float* Whh_f0 = (const float*)d_in[2];
    const float* b_f0   = (const float*)d_in[3];
    const float* Wih_b0 = (const float*)d_in[4];
    const float* Whh_b0 = (const float*)d_in[5];
    const float* b_b0   = (const float*)d_in[6];
    const float* Wih_f1 = (const float*)d_in[7];
    const float* Whh_f1 = (const float*)d_in[8];
    const float* b_f1   = (const float*)d_in[9];
    const float* Wih_b1 = (const float*)d_in[10];
    const float* Whh_b1 = (const float*)d_in[11];
    const float* b_b1   = (const float*)d_in[12];
    const float* Wl     = (const float*)d_in[13];
    const float* bl     = (const float*)d_in[14];
    const float* alpha  = (const float*)d_in[15];
    float* out = (float*)d_out;

    const int smem_rec = (32 * SH_STR + 32 * SX_STR + 16 * 4 * 33) * (int)sizeof(float);
    cudaFuncSetAttribute(lstm_persist<0>, cudaFuncAttributeMaxDynamicSharedMemorySize, smem_rec);
    cudaFuncSetAttribute(lstm_persist<1>, cudaFuncAttributeMaxDynamicSharedMemorySize, smem_rec);

    prep_wp<<<1100, 256>>>(Wih_f0, Wih_b0);
    zero_kernel<<<400, 256>>>(1);
    lstm_persist<0><<<NBLK, 256, smem_rec>>>(x, Whh_f0, b_f0, Whh_b0, b_b0);
    xs1_gemm<<<dim3(50, T, 2), 256>>>(Wih_f1, Wih_b1);
    zero_kernel<<<400, 256>>>(0);
    lstm_persist<1><<<NBLK, 256, smem_rec>>>(nullptr, Whh_f1, b_f1, Whh_b1, b_b1);
    logits_angles<<<T, 640>>>(Wl, bl, alpha);
    coord_scan_kernel<<<1, 32>>>(out);
}

// round 5
// speedup vs baseline: 1.3475x; 1.3475x over previous
#include <cuda_runtime.h>
#include <math.h>

constexpr int T = 512, B = 32, DIN = 41, H = 800;
constexpr int UPB = 12;                       // units per block
constexpr int BPD = 67;                       // blocks per direction (66*12+8)
constexpr int NBLK = 2 * BPD;                 // 134 persistent blocks
constexpr int SHS = 404;                      // smem h row stride (bank-clean, 16B-aligned)
constexpr int SXS = 44;                       // padded input K
typedef unsigned long long ull;

// ---------------- scratch ----------------
__device__ float g_hstate[2][2][B][H];        // [phase][dir][b][k]
__device__ float g_h1[T][B][2 * H];
__device__ float g_h2[T][B][2 * H];
__device__ float g_xs1[2][T][4 * H][B];
__device__ float g_Wp[2][4 * H][SXS];         // zero-padded Wih layer0
__device__ float g_ang[T][B][3];
__device__ int   g_bar[2][T];

// ---------------- helpers ----------------
__device__ __forceinline__ void ffma2(ull& d, ull a, ull b) {
    asm("fma.rn.f32x2 %0, %1, %2, %0;" : "+l"(d) : "l"(a), "l"(b));
}
__device__ __forceinline__ float hadd(ull v) {
    float lo, hi;
    asm("mov.b64 {%0,%1}, %2;" : "=f"(lo), "=f"(hi) : "l"(v));
    return lo + hi;
}
__device__ __forceinline__ float sigm(float x) { return 1.0f / (1.0f + expf(-x)); }

// ---------------- init ----------------
__global__ void zero_kernel(int zero_bar) {
    int i = blockIdx.x * blockDim.x + threadIdx.x;
    if (i < 2 * 2 * B * H) ((float*)g_hstate)[i] = 0.0f;
    if (zero_bar && i < 2 * T) ((int*)g_bar)[i] = 0;
}

__global__ void prep_wp(const float* __restrict__ Wf, const float* __restrict__ Wb) {
    int i = blockIdx.x * blockDim.x + threadIdx.x;
    if (i >= 2 * 4 * H * SXS) return;
    int dir = i / (4 * H * SXS);
    int rem = i % (4 * H * SXS);
    int r = rem / SXS, k = rem % SXS;
    const float* W = dir ? Wb : Wf;
    ((float*)g_Wp)[i] = (k < DIN) ? W[r * DIN + k] : 0.0f;
}

// ---------------- persistent bi-LSTM layer ----------------
// 134 blocks x 192 threads = (half<2, u<12, bq<8). Thread (half0) owns ALL 4
// gates of unit u for batches {bq, bq+8, bq+16, bq+24}; c stays in registers.
template <int LAYER>
__global__ void __launch_bounds__(192, 1) lstm_persist(
    const float* __restrict__ x,
    const float* __restrict__ Whh_f, const float* __restrict__ b_f,
    const float* __restrict__ Whh_b, const float* __restrict__ b_b)
{
    extern __shared__ float smem[];
    float* sh0  = smem;                       // 32 x 404 (k 0..399)
    float* sh1  = smem + 32 * SHS;            // 32 x 404 (k 400..799)
    float* sx   = smem + 2 * 32 * SHS;        // 32 x 44
    float* sred = sx + 32 * SXS;              // [12][4][32]

    const int tid  = threadIdx.x;
    const int half = tid / 96;
    const int r96  = tid % 96;
    const int u    = r96 >> 3;
    const int bq   = r96 & 7;

    const int blk = blockIdx.x;
    const int dir = (blk >= BPD);
    const int ublk = dir ? blk - BPD : blk;
    const int UB = (800 - ublk * UPB < UPB) ? (800 - ublk * UPB) : UPB;
    const bool act = (u < UB);
    const int ug = ublk * UPB + (act ? u : 0);

    const float* __restrict__ Whh = dir ? Whh_b : Whh_f;
    const float* __restrict__ bia = dir ? b_b : b_f;

    const float* wp[4];
    float bias[4];
#pragma unroll
    for (int g = 0; g < 4; g++) {
        wp[g] = Whh + (size_t)(g * H + ug) * H + half * 400;
        bias[g] = act ? __ldg(&bia[g * H + ug]) : 0.0f;
    }
    float creg[4] = {0.f, 0.f, 0.f, 0.f};
    const float* shh = half ? sh1 : sh0;

    for (int s = 0; s < T; s++) {
        const int t = dir ? (T - 1 - s) : s;
        const int ph = s & 1;

        // stage h (L2-coherent reads), split by k-half
        const float* hsrc = &g_hstate[ph][dir][0][0];
        for (int i = tid; i < 32 * 200; i += 192) {
            int b = i / 200, kq = i % 200;
            float4 v = __ldcg((const float4*)(hsrc + b * H + kq * 4));
            int hs = (kq >= 100);
            float* dst = (hs ? sh1 : sh0) + b * SHS + (kq - hs * 100) * 4;
            *(float4*)dst = v;
        }
        if (LAYER == 0) {
            for (int i = tid; i < 32 * SXS; i += 192) {
                int b = i / SXS, k = i % SXS;
                sx[i] = (k < DIN) ? __ldg(&x[(t * B + b) * DIN + k]) : 0.0f;
            }
        }
        __syncthreads();

        ull acc[16];
#pragma unroll
        for (int j = 0; j < 16; j++) acc[j] = 0;

        if (act) {
            const float* hb = shh + bq * SHS;
#pragma unroll 2
            for (int k = 0; k < 400; k += 4) {
                ull w[8];
#pragma unroll
                for (int g = 0; g < 4; g++) {
                    float4 wv = __ldg((const float4*)(wp[g] + k));
                    w[2 * g] = ((ull*)&wv)[0]; w[2 * g + 1] = ((ull*)&wv)[1];
                }
#pragma unroll
                for (int i = 0; i < 4; i++) {
                    float4 hv = *(const float4*)(hb + i * (8 * SHS) + k);
                    ull hlo = ((ull*)&hv)[0], hhi = ((ull*)&hv)[1];
#pragma unroll
                    for (int g = 0; g < 4; g++) {
                        ffma2(acc[g * 4 + i], w[2 * g], hlo);
                        ffma2(acc[g * 4 + i], w[2 * g + 1], hhi);
                    }
                }
            }
            if (LAYER == 0 && half == 1) {
                const float* hb2 = sx + bq * SXS;
#pragma unroll
                for (int k = 0; k < SXS; k += 4) {
                    ull w[8];
#pragma unroll
                    for (int g = 0; g < 4; g++) {
                        float4 wv = *(const float4*)(&g_Wp[dir][g * H + ug][k]);
                        w[2 * g] = ((ull*)&wv)[0]; w[2 * g + 1] = ((ull*)&wv)[1];
                    }
#pragma unroll
                    for (int i = 0; i < 4; i++) {
                        float4 hv = *(const float4*)(hb2 + i * (8 * SXS) + k);
                        ull hlo = ((ull*)&hv)[0], hhi = ((ull*)&hv)[1];
#pragma unroll
                        for (int g = 0; g < 4; g++) {
                            ffma2(acc[g * 4 + i], w[2 * g], hlo);
                            ffma2(acc[g * 4 + i], w[2 * g + 1], hhi);
                        }
                    }
                }
            }
        }

        if (half == 1 && act) {
#pragma unroll
            for (int g = 0; g < 4; g++)
#pragma unroll
                for (int i = 0; i < 4; i++)
                    sred[(u * 4 + g) * 32 + bq + 8 * i] = hadd(acc[g * 4 + i]);
        }
        __syncthreads();

        if (half == 0 && act) {
#pragma unroll
            for (int i = 0; i < 4; i++) {
                int b = bq + 8 * i;
                float e[4];
#pragma unroll
                for (int g = 0; g < 4; g++) {
                    e[g] = hadd(acc[g * 4 + i]) + sred[(u * 4 + g) * 32 + b] + bias[g];
                    if (LAYER == 1)
                        e[g] += __ldg(&g_xs1[dir][t][g * H + ug][b]);
                }
                float cn = sigm(e[1]) * creg[i] + sigm(e[0]) * tanhf(e[2]);
                float hn = sigm(e[3]) * tanhf(cn);
                creg[i] = cn;
                g_hstate[ph ^ 1][dir][b][ug] = hn;
                if (LAYER == 0) g_h1[t][b][dir * H + ug] = hn;
                else            g_h2[t][b][dir * H + ug] = hn;
            }
        }

        __syncthreads();
        if (s < T - 1) {
            if (tid == 0) {
                __threadfence();
                atomicAdd(&g_bar[LAYER][s], 1);
                while (((volatile int*)g_bar[LAYER])[s] < NBLK) {}
                __threadfence();
            }
            __syncthreads();
        }
    }
}

// ---------------- xs1 = Wih1 @ h1 : 4 rows x 2 t x 4 batches per thread ----
__global__ void __launch_bounds__(256) xs1_gemm(
    const float* __restrict__ Wf, const float* __restrict__ Wb)
{
    const int gt = blockIdx.x, tp = blockIdx.y, dir = blockIdx.z;
    const float* __restrict__ W = dir ? Wb : Wf;
    const int t0 = 2 * tp;

    __shared__ alignas(16) float sh[2][32 * 164];

    const int tid = threadIdx.x;
    const int rp = tid >> 3, bq = tid & 7;
    const int r0 = gt * 128 + rp * 4;

    const float* wpr[4];
#pragma unroll
    for (int g = 0; g < 4; g++) wpr[g] = W + (size_t)(r0 + g) * (2 * H);

    ull acc[32];   // [g][tq*4+i]
#pragma unroll
    for (int j = 0; j < 32; j++) acc[j] = 0;

    for (int k0 = 0; k0 < 2 * H; k0 += 160) {
        __syncthreads();
        for (int i = tid; i < 2 * 32 * 40; i += 256) {
            int tq = i / 1280, rem = i % 1280;
            int b = rem / 40, kq = rem % 40;
            *(float4*)&sh[tq][b * 164 + kq * 4] =
                __ldg((const float4*)(&g_h1[t0 + tq][b][k0 + kq * 4]));
        }
        __syncthreads();
#pragma unroll 2
        for (int k = 0; k < 160; k += 4) {
            ull w[8];
#pragma unroll
            for (int g = 0; g < 4; g++) {
                float4 wv = __ldg((const float4*)(wpr[g] + k0 + k));
                w[2 * g] = ((ull*)&wv)[0]; w[2 * g + 1] = ((ull*)&wv)[1];
            }
#pragma unroll
            for (int tq = 0; tq < 2; tq++)
#pragma unroll
                for (int i = 0; i < 4; i++) {
                    float4 hv = *(const float4*)(&sh[tq][(bq + 8 * i) * 164 + k]);
                    ull hlo = ((ull*)&hv)[0], hhi = ((ull*)&hv)[1];
#pragma unroll
                    for (int g = 0; g < 4; g++) {
                        ffma2(acc[g * 8 + tq * 4 + i], w[2 * g], hlo);
                        ffma2(acc[g * 8 + tq * 4 + i], w[2 * g + 1], hhi);
                    }
                }
        }
    }
#pragma unroll
    for (int g = 0; g < 4; g++)
#pragma unroll
        for (int tq = 0; tq < 2; tq++)
#pragma unroll
            for (int i = 0; i < 4; i++)
                g_xs1[dir][t0 + tq][r0 + g][bq + 8 * i] = hadd(acc[g * 8 + tq * 4 + i]);
}

// ---------------- logits -> softmax-folded atan2 -> angles ----------------
__global__ void __launch_bounds__(640) logits_angles(
    const float* __restrict__ Wl, const float* __restrict__ bl,
    const float* __restrict__ alphabet)
{
    const int t = blockIdx.x, tid = threadIdx.x;
    __shared__ float sl[32][21];
    __shared__ float ssin[20][3], scos[20][3];

    if (tid < 60) {
        int a = tid / 3, j = tid % 3;
        float v = alphabet[tid];
        ssin[a][j] = sinf(v); scos[a][j] = cosf(v);
    }
    {
        int a = tid >> 5, b = tid & 31;
        float acc = 0.0f;
        for (int k = 0; k < 2 * H; k += 4) {
            float4 hv = __ldg((const float4*)&g_h2[t][b][k]);
            float4 wv = __ldg((const float4*)&Wl[a * 2 * H + k]);
            acc += hv.x * wv.x + hv.y * wv.y + hv.z * wv.z + hv.w * wv.w;
        }
        sl[b][a] = acc + __ldg(&bl[a]);
    }
    __syncthreads();

    if (tid < 32) {
        int b = tid;
        float m = -1e30f;
#pragma unroll
        for (int a = 0; a < 20; a++) m = fmaxf(m, sl[b][a]);
        float ys[3] = {0, 0, 0}, xc[3] = {0, 0, 0};
#pragma unroll
        for (int a = 0; a < 20; a++) {
            float e = expf(sl[b][a] - m);
#pragma unroll
            for (int j = 0; j < 3; j++) { ys[j] += e * ssin[a][j]; xc[j] += e * scos[a][j]; }
        }
#pragma unroll
        for (int j = 0; j < 3; j++) g_ang[t][b][j] = atan2f(ys[j], xc[j]);
    }
}

// ---------------- NeRF coordinate extension ----------------
__global__ void coord_scan_kernel(float* __restrict__ out)
{
    const int b = threadIdx.x;
    const float rl[3] = {1.458f, 1.525f, 1.33f};
    const float th[3] = {2.124f, 1.941f, 2.028f};
    float rct[3], rst[3];
#pragma unroll
    for (int j = 0; j < 3; j++) { rct[j] = rl[j] * cosf(th[j]); rst[j] = rl[j] * sinf(th[j]); }

    float ax = 0.f, ay = 0.f, az = 0.f;
    float bx = 1.458f, by = 0.f, bz = 0.f;
    float cx = 2.f, cy = 1.f, cz = 0.f;

    for (int n = 0; n < 3 * T; n++) {
        int tt = n / 3, j = n - 3 * tt;
        float phi = g_ang[tt][b][j];
        float bcx = cx - bx, bcy = cy - by, bcz = cz - bz;
        float inv = rsqrtf(bcx * bcx + bcy * bcy + bcz * bcz);
        bcx *= inv; bcy *= inv; bcz *= inv;
        float abx = bx - ax, aby = by - ay, abz = bz - az;
        float nx = aby * bcz - abz * bcy;
        float ny = abz * bcx - abx * bcz;
        float nz = abx * bcy - aby * bcx;
        inv = rsqrtf(nx * nx + ny * ny + nz * nz);
        nx *= inv; ny *= inv; nz *= inv;
        float mx = ny * bcz - nz * bcy;
        float my = nz * bcx - nx * bcz;
        float mz = nx * bcy - ny * bcx;
        float sphi, cphi;
        __sincosf(phi, &sphi, &cphi);
        float dx = cx - rct[j] * bcx + rst[j] * (cphi * mx + sphi * nx);
        float dy = cy - rct[j] * bcy + rst[j] * (cphi * my + sphi * ny);
        float dz = cz - rct[j] * bcz + rst[j] * (cphi * mz + sphi * nz);
        float* o = out + (n * B + b) * 3;
        o[0] = dx; o[1] = dy; o[2] = dz;
        ax = bx; ay = by; az = bz;
        bx = cx; by = cy; bz = cz;
        cx = dx; cy = dy; cz = dz;
    }
}

// ---------------- launch (8 graph nodes) ----------------
extern "C" void kernel_launch(void* const* d_in, const int* in_sizes, int n_in,
                              void* d_out, int out_size)
{
    const float* x      = (const float*)d_in[0];
    const float* Wih_f0 = (const float*)d_in[1];
    const float* Whh_f0 = (const float*)d_in[2];
    const float* b_f0   = (const float*)d_in[3];
    const float* Wih_b0 = (const float*)d_in[4];
    const float* Whh_b0 = (const float*)d_in[5];
    const float* b_b0   = (const float*)d_in[6];
    const float* Wih_f1 = (const float*)d_in[7];
    const float* Whh_f1 = (const float*)d_in[8];
    const float* b_f1   = (const float*)d_in[9];
    const float* Wih_b1 = (const float*)d_in[10];
    const float* Whh_b1 = (const float*)d_in[11];
    const float* b_b1   = (const float*)d_in[12];
    const float* Wl     = (const float*)d_in[13];
    const float* bl     = (const float*)d_in[14];
    const float* alpha  = (const float*)d_in[15];
    float* out = (float*)d_out;

    const int smem_rec = (2 * 32 * SHS + 32 * SXS + UPB * 4 * 32) * (int)sizeof(float);
    cudaFuncSetAttribute(lstm_persist<0>, cudaFuncAttributeMaxDynamicSharedMemorySize, smem_rec);
    cudaFuncSetAttribute(lstm_persist<1>, cudaFuncAttributeMaxDynamicSharedMemorySize, smem_rec);

    prep_wp<<<1100, 256>>>(Wih_f0, Wih_b0);
    zero_kernel<<<400, 256>>>(1);
    lstm_persist<0><<<NBLK, 192, smem_rec>>>(x, Whh_f0, b_f0, Whh_b0, b_b0);
    xs1_gemm<<<dim3(25, 256, 2), 256>>>(Wih_f1, Wih_b1);
    zero_kernel<<<400, 256>>>(0);
    lstm_persist<1><<<NBLK, 192, smem_rec>>>(nullptr, Whh_f1, b_f1, Whh_b1, b_b1);
    logits_angles<<<T, 640>>>(Wl, bl, alpha);
    coord_scan_kernel<<<1, 32>>>(out);
}

// round 6
// speedup vs baseline: 1.4664x; 1.0882x over previous
#include <cuda_runtime.h>
#include <math.h>

constexpr int T = 512, B = 32, DIN = 41, H = 800;
constexpr int UPB = 12;                 // units per block
constexpr int BPD = 67;                 // blocks per direction (66 full + 1x8)
constexpr int NBLK = 2 * BPD;           // 134 persistent blocks
constexpr int SHS = 808;                // smem h row stride (pad: bank-clean)
constexpr int SXS = 52;                 // padded input K (bank-clean)
typedef unsigned long long ull;

// ---------------- scratch ----------------
__device__ float g_hstate[2][2][B][H];  // [phase][dir][b][k]
__device__ float g_h1[T][B][2 * H];
__device__ float g_h2[T][B][2 * H];
__device__ float g_xs1[2][T][4 * H][B];
__device__ float g_Wp[2][4 * H][SXS];   // zero-padded Wih layer0
__device__ float g_ang[T][B][3];
__device__ int   g_bar[2][T];

// ---------------- helpers ----------------
__device__ __forceinline__ void ffma2(ull& d, ull a, ull b) {
    asm("fma.rn.f32x2 %0, %1, %2, %0;" : "+l"(d) : "l"(a), "l"(b));
}
__device__ __forceinline__ float hadd(ull v) {
    float lo, hi;
    asm("mov.b64 {%0,%1}, %2;" : "=f"(lo), "=f"(hi) : "l"(v));
    return lo + hi;
}
__device__ __forceinline__ float sigm(float x) { return 1.0f / (1.0f + expf(-x)); }

// ---------------- init ----------------
__global__ void zero_kernel(int zero_bar) {
    int i = blockIdx.x * blockDim.x + threadIdx.x;
    if (i < 2 * 2 * B * H) ((float*)g_hstate)[i] = 0.0f;
    if (zero_bar && i < 2 * T) ((int*)g_bar)[i] = 0;
}

__global__ void prep_wp(const float* __restrict__ Wf, const float* __restrict__ Wb) {
    int i = blockIdx.x * blockDim.x + threadIdx.x;
    if (i >= 2 * 4 * H * SXS) return;
    int dir = i / (4 * H * SXS);
    int rem = i % (4 * H * SXS);
    int r = rem / SXS, k = rem % SXS;
    const float* W = dir ? Wb : Wf;
    ((float*)g_Wp)[i] = (k < DIN) ? W[r * DIN + k] : 0.0f;
}

// ---------------- persistent bi-LSTM layer ----------------
// 134 blocks x 192 threads. tid -> (ks<8, rg<6, bg<4).
// Compute: thread owns 8 rows (2 units x 4 gates) x 8 batches {bg+4i} x k-slice
// of 100 (1 MAC/byte). k-split reduced via smem; cell update by (u,b) owners
// (u = tid>>4, b = 2*(tid&15)+{0,1}) with c in registers across all 512 steps.
template <int LAYER>
__global__ void __launch_bounds__(192, 1) lstm_persist(
    const float* __restrict__ x,
    const float* __restrict__ Whh_f, const float* __restrict__ b_f,
    const float* __restrict__ Whh_b, const float* __restrict__ b_b)
{
    extern __shared__ float smem[];
    float* sh   = smem;                  // [32][808]
    float* sx   = smem + 32 * SHS;       // [32][52]
    float* sred = sx + 32 * SXS;         // [8ks][4g][12u][32b]

    const int tid = threadIdx.x;
    const int ks  = tid / 24;            // 0..7  (k-slice)
    const int rem = tid % 24;
    const int rg  = rem >> 2;            // 0..5  (unit pair)
    const int bg  = rem & 3;             // 0..3  (batch group)

    const int blk  = blockIdx.x;
    const int dir  = (blk >= BPD);
    const int ublk = dir ? blk - BPD : blk;
    const int UB    = (800 - ublk * UPB < UPB) ? (800 - ublk * UPB) : UPB;
    const int ubase = ublk * UPB;

    const float* __restrict__ Whh = dir ? Whh_b : Whh_f;
    const float* __restrict__ bia = dir ? b_b : b_f;

    const int u0c = (rg * 2     < UB) ? rg * 2     : UB - 1;
    const int u1c = (rg * 2 + 1 < UB) ? rg * 2 + 1 : UB - 1;
    const float* w0  = Whh + (size_t)(ubase + u0c) * H + ks * 100;
    const float* w1  = Whh + (size_t)(ubase + u1c) * H + ks * 100;
    const float* wx0 = &g_Wp[dir][ubase + u0c][0];
    const float* wx1 = &g_Wp[dir][ubase + u1c][0];

    // update-role constants
    const int uu = tid >> 4;             // 0..11
    const int b0 = (tid & 15) * 2;
    const bool updact = (uu < UB);
    float bias_r[4];
#pragma unroll
    for (int g = 0; g < 4; g++)
        bias_r[g] = updact ? __ldg(&bia[g * H + ubase + uu]) : 0.0f;
    float creg0 = 0.0f, creg1 = 0.0f;

    for (int s = 0; s < T; s++) {
        const int t  = dir ? (T - 1 - s) : s;
        const int ph = s & 1;

        // ---- stage h[ph] (global, L1-bypassed) into smem ----
        const float* hsrc = &g_hstate[ph][dir][0][0];
        for (int i = tid; i < 6400; i += 192) {
            int b = i / 200, kq = i - b * 200;
            float4 v = __ldcg((const float4*)(hsrc + i * 4));
            *(float4*)&sh[b * SHS + kq * 4] = v;
        }
        if (LAYER == 0) {
            for (int i = tid; i < 32 * SXS; i += 192) {
                int b = i / SXS, k = i - b * SXS;
                sx[i] = (k < DIN) ? __ldg(&x[(t * B + b) * DIN + k]) : 0.0f;
            }
        }
        __syncthreads();

        // ---- 8x8 register-tile dot products over this thread's k-slice ----
        ull acc[64];
#pragma unroll
        for (int j = 0; j < 64; j++) acc[j] = 0;

        {
            const float* hb = sh + bg * SHS + ks * 100;
            for (int k = 0; k < 100; k += 4) {
                float4 hv[8];
#pragma unroll
                for (int i = 0; i < 8; i++)
                    hv[i] = *(const float4*)(hb + i * (4 * SHS) + k);
#pragma unroll
                for (int g = 0; g < 4; g++) {
#pragma unroll
                    for (int du = 0; du < 2; du++) {
                        const float* wp = du ? w1 : w0;
                        float4 wv = __ldg((const float4*)(wp + g * (4 * H * H / 4) + k));
                        ull wlo = ((const ull*)&wv)[0], whi = ((const ull*)&wv)[1];
                        const int j = g * 2 + du;
#pragma unroll
                        for (int i = 0; i < 8; i++) {
                            ffma2(acc[j * 8 + i], wlo, ((const ull*)&hv[i])[0]);
                            ffma2(acc[j * 8 + i], whi, ((const ull*)&hv[i])[1]);
                        }
                    }
                }
            }
        }
        if (LAYER == 0 && ks == 0) {
            const float* hb2 = sx + bg * SXS;
#pragma unroll
            for (int k = 0; k < SXS; k += 4) {
                float4 hv[8];
#pragma unroll
                for (int i = 0; i < 8; i++)
                    hv[i] = *(const float4*)(hb2 + i * (4 * SXS) + k);
#pragma unroll
                for (int g = 0; g < 4; g++) {
#pragma unroll
                    for (int du = 0; du < 2; du++) {
                        const float* wp = du ? wx1 : wx0;
                        float4 wv = *(const float4*)(wp + g * (800 * SXS) + k);
                        ull wlo = ((const ull*)&wv)[0], whi = ((const ull*)&wv)[1];
                        const int j = g * 2 + du;
#pragma unroll
                        for (int i = 0; i < 8; i++) {
                            ffma2(acc[j * 8 + i], wlo, ((const ull*)&hv[i])[0]);
                            ffma2(acc[j * 8 + i], whi, ((const ull*)&hv[i])[1]);
                        }
                    }
                }
            }
        }

        // ---- write k-slice partials ----
#pragma unroll
        for (int g = 0; g < 4; g++)
#pragma unroll
            for (int du = 0; du < 2; du++) {
                const int row = (ks * 4 + g) * 12 + rg * 2 + du;
                const int j = g * 2 + du;
#pragma unroll
                for (int i = 0; i < 8; i++)
                    sred[row * 32 + bg + 4 * i] = hadd(acc[j * 8 + i]);
            }
        __syncthreads();

        // ---- cell update: unit uu, batches b0,b0+1 ----
        if (updact) {
            float e0[4], e1[4];
#pragma unroll
            for (int g = 0; g < 4; g++) {
                float s0 = 0.f, s1 = 0.f;
#pragma unroll
                for (int k2 = 0; k2 < 8; k2++) {
                    float2 v = *(const float2*)&sred[((k2 * 4 + g) * 12 + uu) * 32 + b0];
                    s0 += v.x; s1 += v.y;
                }
                e0[g] = s0 + bias_r[g];
                e1[g] = s1 + bias_r[g];
                if (LAYER == 1) {
                    float2 v = __ldg((const float2*)&g_xs1[dir][t][g * H + ubase + uu][b0]);
                    e0[g] += v.x; e1[g] += v.y;
                }
            }
            float cn0 = sigm(e0[1]) * creg0 + sigm(e0[0]) * tanhf(e0[2]);
            float hn0 = sigm(e0[3]) * tanhf(cn0);
            float cn1 = sigm(e1[1]) * creg1 + sigm(e1[0]) * tanhf(e1[2]);
            float hn1 = sigm(e1[3]) * tanhf(cn1);
            creg0 = cn0; creg1 = cn1;
            const int ug = ubase + uu;
            g_hstate[ph ^ 1][dir][b0][ug]     = hn0;
            g_hstate[ph ^ 1][dir][b0 + 1][ug] = hn1;
            if (LAYER == 0) {
                g_h1[t][b0][dir * H + ug]     = hn0;
                g_h1[t][b0 + 1][dir * H + ug] = hn1;
            } else {
                g_h2[t][b0][dir * H + ug]     = hn0;
                g_h2[t][b0 + 1][dir * H + ug] = hn1;
            }
        }

        __syncthreads();
        if (s < T - 1) {
            if (tid == 0) {
                __threadfence();
                atomicAdd(&g_bar[LAYER][s], 1);
                while (((volatile int*)g_bar[LAYER])[s] < NBLK) {}
                __threadfence();
            }
            __syncthreads();
        }
    }
}

// ---------------- xs1 = Wih1 @ h1 : 8 rows x (2 t x 4 b) per thread ----------
// 128 threads = (rowg<16, bq<8); 1 MAC/byte; 2 blocks/SM.
__global__ void __launch_bounds__(128, 2) xs1_gemm(
    const float* __restrict__ Wf, const float* __restrict__ Wb)
{
    const int gt = blockIdx.x, tp = blockIdx.y, dir = blockIdx.z;
    const float* __restrict__ W = dir ? Wb : Wf;
    const int t0 = tp * 2;

    __shared__ alignas(16) float sh[2][32 * 164];

    const int tid = threadIdx.x;
    const int rowg = tid >> 3, bq = tid & 7;
    const int r0 = gt * 128 + rowg * 8;
    const float* wbase = W + (size_t)r0 * (2 * H);

    ull acc[64];                         // [j<8 rows][c<8 = tq*4+i]
#pragma unroll
    for (int j = 0; j < 64; j++) acc[j] = 0;

    for (int k0 = 0; k0 < 2 * H; k0 += 160) {
        __syncthreads();
        for (int i2 = tid; i2 < 2560; i2 += 128) {
            int tq = i2 / 1280, rem = i2 - tq * 1280;
            int b = rem / 40, kq = rem - b * 40;
            *(float4*)&sh[tq][b * 164 + kq * 4] =
                __ldg((const float4*)(&g_h1[t0 + tq][b][k0 + kq * 4]));
        }
        __syncthreads();
        for (int k = 0; k < 160; k += 4) {
            float4 hv[8];
#pragma unroll
            for (int tq = 0; tq < 2; tq++)
#pragma unroll
                for (int i = 0; i < 4; i++)
                    hv[tq * 4 + i] = *(const float4*)&sh[tq][(bq + 8 * i) * 164 + k];
#pragma unroll
            for (int j = 0; j < 8; j++) {
                float4 wv = __ldg((const float4*)(wbase + j * (2 * H) + k0 + k));
                ull wlo = ((const ull*)&wv)[0], whi = ((const ull*)&wv)[1];
#pragma unroll
                for (int c = 0; c < 8; c++) {
                    ffma2(acc[j * 8 + c], wlo, ((const ull*)&hv[c])[0]);
                    ffma2(acc[j * 8 + c], whi, ((const ull*)&hv[c])[1]);
                }
            }
        }
    }
#pragma unroll
    for (int j = 0; j < 8; j++)
#pragma unroll
        for (int tq = 0; tq < 2; tq++)
#pragma unroll
            for (int i = 0; i < 4; i++)
                g_xs1[dir][t0 + tq][r0 + j][bq + 8 * i] = hadd(acc[j * 8 + tq * 4 + i]);
}

// ---------------- logits -> softmax-folded atan2 -> angles ----------------
__global__ void __launch_bounds__(640) logits_angles(
    const float* __restrict__ Wl, const float* __restrict__ bl,
    const float* __restrict__ alphabet)
{
    const int t = blockIdx.x, tid = threadIdx.x;
    __shared__ float sl[32][21];
    __shared__ float ssin[20][3], scos[20][3];

    if (tid < 60) {
        int a = tid / 3, j = tid % 3;
        float v = alphabet[tid];
        ssin[a][j] = sinf(v); scos[a][j] = cosf(v);
    }
    {
        int a = tid >> 5, b = tid & 31;
        float acc = 0.0f;
        for (int k = 0; k < 2 * H; k += 4) {
            float4 hv = __ldg((const float4*)&g_h2[t][b][k]);
            float4 wv = __ldg((const float4*)&Wl[a * 2 * H + k]);
            acc += hv.x * wv.x + hv.y * wv.y + hv.z * wv.z + hv.w * wv.w;
        }
        sl[b][a] = acc + __ldg(&bl[a]);
    }
    __syncthreads();

    if (tid < 32) {
        int b = tid;
        float m = -1e30f;
#pragma unroll
        for (int a = 0; a < 20; a++) m = fmaxf(m, sl[b][a]);
        float ys[3] = {0, 0, 0}, xc[3] = {0, 0, 0};
#pragma unroll
        for (int a = 0; a < 20; a++) {
            float e = expf(sl[b][a] - m);
#pragma unroll
            for (int j = 0; j < 3; j++) { ys[j] += e * ssin[a][j]; xc[j] += e * scos[a][j]; }
        }
#pragma unroll
        for (int j = 0; j < 3; j++) g_ang[t][b][j] = atan2f(ys[j], xc[j]);
    }
}

// ---------------- NeRF coordinate extension ----------------
__global__ void coord_scan_kernel(float* __restrict__ out)
{
    const int b = threadIdx.x;
    const float rl[3] = {1.458f, 1.525f, 1.33f};
    const float th[3] = {2.124f, 1.941f, 2.028f};
    float rct[3], rst[3];
#pragma unroll
    for (int j = 0; j < 3; j++) { rct[j] = rl[j] * cosf(th[j]); rst[j] = rl[j] * sinf(th[j]); }

    float ax = 0.f, ay = 0.f, az = 0.f;
    float bx = 1.458f, by = 0.f, bz = 0.f;
    float cx = 2.f, cy = 1.f, cz = 0.f;

    for (int n = 0; n < 3 * T; n++) {
        int tt = n / 3, j = n - 3 * tt;
        float phi = g_ang[tt][b][j];
        float bcx = cx - bx, bcy = cy - by, bcz = cz - bz;
        float inv = rsqrtf(bcx * bcx + bcy * bcy + bcz * bcz);
        bcx *= inv; bcy *= inv; bcz *= inv;
        float abx = bx - ax, aby = by - ay, abz = bz - az;
        float nx = aby * bcz - abz * bcy;
        float ny = abz * bcx - abx * bcz;
        float nz = abx * bcy - aby * bcx;
        inv = rsqrtf(nx * nx + ny * ny + nz * nz);
        nx *= inv; ny *= inv; nz *= inv;
        float mx = ny * bcz - nz * bcy;
        float my = nz * bcx - nx * bcz;
        float mz = nx * bcy - ny * bcx;
        float sphi, cphi;
        __sincosf(phi, &sphi, &cphi);
        float dx = cx - rct[j] * bcx + rst[j] * (cphi * mx + sphi * nx);
        float dy = cy - rct[j] * bcy + rst[j] * (cphi * my + sphi * ny);
        float dz = cz - rct[j] * bcz + rst[j] * (cphi * mz + sphi * nz);
        float* o = out + (n * B + b) * 3;
        o[0] = dx; o[1] = dy; o[2] = dz;
        ax = bx; ay = by; az = bz;
        bx = cx; by = cy; bz = cz;
        cx = dx; cy = dy; cz = dz;
    }
}

// ---------------- launch (8 graph nodes) ----------------
extern "C" void kernel_launch(void* const* d_in, const int* in_sizes, int n_in,
                              void* d_out, int out_size)
{
    const float* x      = (const float*)d_in[0];
    const float* Wih_f0 = (const float*)d_in[1];
    const float* Whh_f0 = (const float*)d_in[2];
    const float* b_f0   = (const float*)d_in[3];
    const float* Wih_b0 = (const float*)d_in[4];
    const float* Whh_b0 = (const float*)d_in[5];
    const float* b_b0   = (const float*)d_in[6];
    const float* Wih_f1 = (const float*)d_in[7];
    const float* Whh_f1 = (const float*)d_in[8];
    const float* b_f1   = (const float*)d_in[9];
    const float* Wih_b1 = (const float*)d_in[10];
    const float* Whh_b1 = (const float*)d_in[11];
    const float* b_b1   = (const float*)d_in[12];
    const float* Wl     = (const float*)d_in[13];
    const float* bl     = (const float*)d_in[14];
    const float* alpha  = (const float*)d_in[15];
    float* out = (float*)d_out;

    const int smem_rec = (32 * SHS + 32 * SXS + 8 * 4 * 12 * 32) * (int)sizeof(float);
    cudaFuncSetAttribute(lstm_persist<0>, cudaFuncAttributeMaxDynamicSharedMemorySize, smem_rec);
    cudaFuncSetAttribute(lstm_persist<1>, cudaFuncAttributeMaxDynamicSharedMemorySize, smem_rec);

    prep_wp<<<1300, 256>>>(Wih_f0, Wih_b0);
    zero_kernel<<<400, 256>>>(1);
    lstm_persist<0><<<NBLK, 192, smem_rec>>>(x, Whh_f0, b_f0, Whh_b0, b_b0);
    xs1_gemm<<<dim3(25, 256, 2), 128>>>(Wih_f1, Wih_b1);
    zero_kernel<<<400, 256>>>(0);
    lstm_persist<1><<<NBLK, 192, smem_rec>>>(nullptr, Whh_f1, b_f1, Whh_b1, b_b1);
    logits_angles<<<T, 640>>>(Wl, bl, alpha);
    coord_scan_kernel<<<1, 32>>>(out);
}